// round 16
// baseline (speedup 1.0000x reference)
#include <cuda_runtime.h>
#include <cuda_fp16.h>
#include <cstdint>

// Problem constants
constexpr int Vv = 50257, Cc = 384, Tt = 1024, Hh = 6, HSs = 64, NLl = 3, Bb = 2;
constexpr int M_ROWS = Bb * Tt;   // 2048
constexpr int BH = Bb * Hh;       // 12
constexpr int V_PAD = 50304;      // 393 * 128
constexpr int QKV_P = 3 * Cc;     // 1152

// ---------------- scratch (__device__ globals; no allocation allowed) --------
__device__ float g_h[M_ROWS * Cc];
__device__ __half g_aH[M_ROWS * Cc];
__device__ __half g_qkvH[M_ROWS * QKV_P];
__device__ __half g_attH[M_ROWS * Cc];
__device__ __half g_mH[M_ROWS * Cc];
__device__ __half g_P[(size_t)BH * Tt * Tt];
__device__ float g_psum[BH * 8 * Tt];
__device__ __half g_WqkvT[NLl * QKV_P * Cc];
__device__ float g_bqkv[NLl * QKV_P];
__device__ __half g_WoT[NLl * Cc * Cc];
__device__ __half g_W1T[NLl * Cc * Cc];
__device__ __half g_W2T[NLl * Cc * Cc];
__device__ __half g_hH[M_ROWS * Cc];
__device__ __half g_WlmH[(size_t)V_PAD * Cc];

// ---------------- unified prep (weights + embedding, one launch) -------------
constexpr int NB_WLM = (V_PAD / 64) * (Cc / 64);
constexpr int NB_TRA = (Cc / 32) * (Cc / 32) * 3 * NLl;
constexpr int QKV_ELEMS = NLl * QKV_P * Cc + NLl * QKV_P;
constexpr int NB_QKV = (QKV_ELEMS + 255) / 256;
constexpr int NB_EMB = (M_ROWS * Cc + 255) / 256;

__global__ __launch_bounds__(256)
void prep_kernel(const float* __restrict__ Wlm, __half* __restrict__ Bt,
                 const float* __restrict__ Wo, const float* __restrict__ W1,
                 const float* __restrict__ W2,
                 __half* __restrict__ To, __half* __restrict__ T1, __half* __restrict__ T2,
                 const float* __restrict__ Wq, const float* __restrict__ Wk,
                 const float* __restrict__ Wv,
                 const float* __restrict__ bq, const float* __restrict__ bk,
                 const float* __restrict__ bv,
                 __half* __restrict__ OW, float* __restrict__ OB,
                 const int* __restrict__ x, const float* __restrict__ tok,
                 const float* __restrict__ pos, float* __restrict__ h) {
    __shared__ float tile[64 * 65];
    int bid = blockIdx.x;
    int tid = threadIdx.x;

    if (bid < NB_WLM) {
        int n0 = (bid % (V_PAD / 64)) * 64, k0 = (bid / (V_PAD / 64)) * 64;
#pragma unroll
        for (int it = 0; it < 16; it++) {
            int idx = tid + it * 256;
            int r = idx >> 6, c = idx & 63;
            int n = n0 + c;
            tile[r * 65 + c] = (n < Vv) ? Wlm[(size_t)(k0 + r) * Vv + n] : 0.f;
        }
        __syncthreads();
#pragma unroll
        for (int it = 0; it < 2; it++) {
            int idx = tid + it * 256;
            int n = idx >> 3, kc = idx & 7;
            __half hv[8];
#pragma unroll
            for (int j = 0; j < 8; j++) hv[j] = __float2half(tile[(kc * 8 + j) * 65 + n]);
            *reinterpret_cast<uint4*>(Bt + (size_t)(n0 + n) * Cc + k0 + kc * 8) =
                *reinterpret_cast<const uint4*>(hv);
        }
    } else if (bid < NB_WLM + NB_TRA) {
        int id = bid - NB_WLM;
        int id2 = id % 144;
        int xt = id2 % 12, yt = id2 / 12;
        int z = id / 144;
        int wi = z % 3, l = z / 3;
        const float* W = ((wi == 0) ? Wo : (wi == 1) ? W1 : W2) + (size_t)l * Cc * Cc;
        __half* T = ((wi == 0) ? To : (wi == 1) ? T1 : T2) + (size_t)l * Cc * Cc;
        int n0 = xt * 32, k0 = yt * 32;
        int tx = tid & 31, ty = tid >> 5;
        for (int dy = ty; dy < 32; dy += 8)
            tile[dy * 33 + tx] = W[(size_t)(k0 + dy) * Cc + n0 + tx];
        __syncthreads();
        for (int dy = ty; dy < 32; dy += 8)
            T[(size_t)(n0 + dy) * Cc + k0 + tx] = __float2half(tile[tx * 33 + dy]);
    } else if (bid < NB_WLM + NB_TRA + NB_QKV) {
        int i = (bid - NB_WLM - NB_TRA) * 256 + tid;
        int total_w = NLl * QKV_P * Cc;
        if (i < total_w) {
            int k = i % Cc;
            int n = (i / Cc) % QKV_P;
            int l = i / (Cc * QKV_P);
            int sel = n / Cc, hh = (n % Cc) / HSs, s = n % HSs;
            const float* W = (sel == 0) ? Wq : (sel == 1) ? Wk : Wv;
            OW[i] = __float2half(W[(((size_t)l * Hh + hh) * Cc + k) * HSs + s]);
        } else {
            int j = i - total_w;
            if (j < NLl * QKV_P) {
                int n = j % QKV_P, l = j / QKV_P;
                int sel = n / Cc, hh = (n % Cc) / HSs, s = n % HSs;
                const float* B = (sel == 0) ? bq : (sel == 1) ? bk : bv;
                OB[j] = B[((size_t)l * Hh + hh) * HSs + s];
            }
        }
    } else {
        int i = (bid - NB_WLM - NB_TRA - NB_QKV) * 256 + tid;
        if (i < M_ROWS * Cc) {
            int row = i / Cc, c = i % Cc;
            int t = row % Tt;
            h[i] = tok[(size_t)x[row] * Cc + c] + pos[t * Cc + c];
        }
    }
}

// ---------------- layernorm (vectorized, fp16 out) ---------------------------
__global__ void ln_kernel(const float* __restrict__ x, const float* __restrict__ g,
                          const float* __restrict__ b, __half* __restrict__ y) {
    int row = blockIdx.x;
    const float4* xr4 = reinterpret_cast<const float4*>(x + (size_t)row * Cc);
    float4 v = make_float4(0.f, 0.f, 0.f, 0.f);
    int tid = threadIdx.x;
    if (tid < 96) v = xr4[tid];
    float lsum = v.x + v.y + v.z + v.w;
    float lsq = v.x * v.x + v.y * v.y + v.z * v.z + v.w * v.w;
    __shared__ float sh[64];
    int lane = tid & 31, wid = tid >> 5;
#pragma unroll
    for (int o = 16; o; o >>= 1) {
        lsum += __shfl_xor_sync(0xffffffffu, lsum, o);
        lsq  += __shfl_xor_sync(0xffffffffu, lsq,  o);
    }
    if (lane == 0) { sh[wid] = lsum; sh[wid + 32] = lsq; }
    __syncthreads();
    if (tid == 0) {
        float s = 0.f, q = 0.f;
        for (int w = 0; w < 4; w++) { s += sh[w]; q += sh[w + 32]; }
        sh[0] = s; sh[32] = q;
    }
    __syncthreads();
    float mu = sh[0] / Cc;
    float var = sh[32] / Cc - mu * mu;
    float rstd = rsqrtf(var + 1e-5f);
    if (tid < 96) {
        const float4 g4 = reinterpret_cast<const float4*>(g)[tid];
        const float4 b4 = reinterpret_cast<const float4*>(b)[tid];
        __half2 o0 = __floats2half2_rn((v.x - mu) * rstd * g4.x + b4.x,
                                       (v.y - mu) * rstd * g4.y + b4.y);
        __half2 o1 = __floats2half2_rn((v.z - mu) * rstd * g4.z + b4.z,
                                       (v.w - mu) * rstd * g4.w + b4.w);
        uint2 pack;
        pack.x = *reinterpret_cast<uint32_t*>(&o0);
        pack.y = *reinterpret_cast<uint32_t*>(&o1);
        reinterpret_cast<uint2*>(y + (size_t)row * Cc)[tid] = pack;
    }
}

// ---------------- common asm helpers ----------------------------------------
__device__ __forceinline__ uint32_t smem_u32(const void* p) {
    uint32_t a;
    asm("{ .reg .u64 t; cvta.to.shared.u64 t, %1; cvt.u32.u64 %0, t; }" : "=r"(a) : "l"(p));
    return a;
}
__device__ __forceinline__ void cp_async16(uint32_t saddr, const void* g) {
    asm volatile("cp.async.cg.shared.global [%0], [%1], 16;" :: "r"(saddr), "l"(g) : "memory");
}
__device__ __forceinline__ void cp_commit() {
    asm volatile("cp.async.commit_group;" ::: "memory");
}
template<int N>
__device__ __forceinline__ void cp_wait() {
    asm volatile("cp.async.wait_group %0;" :: "n"(N) : "memory");
}
__device__ __forceinline__ void ldm_x4(uint32_t* r, uint32_t addr) {
    asm volatile("ldmatrix.sync.aligned.m8n8.x4.shared.b16 {%0,%1,%2,%3}, [%4];"
                 : "=r"(r[0]), "=r"(r[1]), "=r"(r[2]), "=r"(r[3]) : "r"(addr));
}
__device__ __forceinline__ void ldm_x4_trans(uint32_t* r, uint32_t addr) {
    asm volatile("ldmatrix.sync.aligned.m8n8.x4.trans.shared.b16 {%0,%1,%2,%3}, [%4];"
                 : "=r"(r[0]), "=r"(r[1]), "=r"(r[2]), "=r"(r[3]) : "r"(addr));
}
__device__ __forceinline__ void mma_f16(float* c, const uint32_t* a, const uint32_t* b) {
    asm volatile(
        "mma.sync.aligned.m16n8k16.row.col.f32.f16.f16.f32 "
        "{%0,%1,%2,%3}, {%4,%5,%6,%7}, {%8,%9}, {%0,%1,%2,%3};"
        : "+f"(c[0]), "+f"(c[1]), "+f"(c[2]), "+f"(c[3])
        : "r"(a[0]), "r"(a[1]), "r"(a[2]), "r"(a[3]), "r"(b[0]), "r"(b[1]));
}

// ================= fp16 layer GEMM: CTA 64x128, K-tile 64, 3-stage ===========
constexpr int H16_NKT = Cc / 64;
constexpr int H16_STAGE = 24576;
constexpr int H16_SMEM = 3 * H16_STAGE;

template<int FLAGS>  // 1=relu, 2=accumulate fp32, 16=also fp16 aux copy
__global__ __launch_bounds__(256, 2)
void h16_gemm_kernel(const __half* __restrict__ A, const __half* __restrict__ Bt,
                     const float* __restrict__ bias, void* __restrict__ Cv,
                     __half* __restrict__ aux, int ldc) {
    extern __shared__ __half smh[];
    int tid = threadIdx.x;
    int warp = tid >> 5, lane = tid & 31;
    int wm = warp & 1, wn = warp >> 1;
    int grp = lane >> 2, tig = lane & 3;
    int lr = lane & 7, sub = lane >> 3;
    int m0 = blockIdx.x * 64, n0 = blockIdx.y * 128;
    const __half* Ab = A + (size_t)m0 * Cc;
    const __half* Bb = Bt + (size_t)n0 * Cc;
    uint32_t sbase = smem_u32(smh);

    auto issue = [&](int kt, int stage) {
        uint32_t as = sbase + stage * (uint32_t)H16_STAGE;
        uint32_t bs = as + 8192u;
#pragma unroll
        for (int it = 0; it < 2; it++) {
            int slot = tid + it * 256;
            int r = slot >> 3, c = slot & 7;
            uint32_t so = (uint32_t)(r * 128 + ((c ^ (r & 7)) << 4));
            cp_async16(as + so, Ab + (size_t)r * Cc + kt * 64 + c * 8);
        }
#pragma unroll
        for (int it = 0; it < 4; it++) {
            int slot = tid + it * 256;
            int r = slot >> 3, c = slot & 7;
            uint32_t so = (uint32_t)(r * 128 + ((c ^ (r & 7)) << 4));
            cp_async16(bs + so, Bb + (size_t)r * Cc + kt * 64 + c * 8);
        }
    };

    float acc[2][4][4];
#pragma unroll
    for (int i = 0; i < 2; i++)
#pragma unroll
        for (int j = 0; j < 4; j++)
#pragma unroll
            for (int q = 0; q < 4; q++) acc[i][j][q] = 0.f;

    int rowA[2], rowB[2];
#pragma unroll
    for (int fm = 0; fm < 2; fm++) rowA[fm] = wm * 32 + fm * 16 + (sub & 1) * 8 + lr;
#pragma unroll
    for (int p = 0; p < 2; p++) rowB[p] = wn * 32 + p * 16 + (sub >> 1) * 8 + lr;
    int chA = sub >> 1, chB = sub & 1;

    issue(0, 0); cp_commit();
    issue(1, 1); cp_commit();

    int stage = 0;
#pragma unroll 1
    for (int kt = 0; kt < H16_NKT; kt++) {
        if (kt + 1 < H16_NKT) { cp_wait<1>(); } else { cp_wait<0>(); }
        __syncthreads();
        if (kt + 2 < H16_NKT) {
            int ns = stage + 2; if (ns >= 3) ns -= 3;
            issue(kt + 2, ns);
            cp_commit();
        }
        uint32_t as = sbase + stage * (uint32_t)H16_STAGE;
        uint32_t bs = as + 8192u;
#pragma unroll
        for (int k16 = 0; k16 < 4; k16++) {
            int cb = k16 * 2;
            uint32_t afr[2][4];
#pragma unroll
            for (int fm = 0; fm < 2; fm++) {
                int r = rowA[fm];
                ldm_x4(afr[fm], as + r * 128 + (((cb + chA) ^ (r & 7)) << 4));
            }
            uint32_t bfr[2][4];
#pragma unroll
            for (int p = 0; p < 2; p++) {
                int r = rowB[p];
                ldm_x4(bfr[p], bs + r * 128 + (((cb + chB) ^ (r & 7)) << 4));
            }
#pragma unroll
            for (int fm = 0; fm < 2; fm++)
#pragma unroll
                for (int fn = 0; fn < 4; fn++)
                    mma_f16(acc[fm][fn], afr[fm], &bfr[fn >> 1][(fn & 1) * 2]);
        }
        if (++stage >= 3) stage = 0;
    }

#pragma unroll
    for (int fm = 0; fm < 2; fm++) {
        int m_lo = m0 + wm * 32 + fm * 16 + grp;
        int m_hi = m_lo + 8;
#pragma unroll
        for (int fn = 0; fn < 4; fn++) {
            int n = n0 + wn * 32 + fn * 8 + tig * 2;
#pragma unroll
            for (int e = 0; e < 2; e++) {
                int nn = n + e;
                float bv = bias[nn];
                float v0 = acc[fm][fn][e]     + bv;
                float v1 = acc[fm][fn][e + 2] + bv;
                if (FLAGS & 1) { v0 = fmaxf(v0, 0.f); v1 = fmaxf(v1, 0.f); }
                if constexpr ((FLAGS & 2) != 0) {
                    float* C = (float*)Cv;
                    v0 += C[(size_t)m_lo * ldc + nn];
                    v1 += C[(size_t)m_hi * ldc + nn];
                    C[(size_t)m_lo * ldc + nn] = v0;
                    C[(size_t)m_hi * ldc + nn] = v1;
                    if constexpr ((FLAGS & 16) != 0) {
                        aux[(size_t)m_lo * ldc + nn] = __float2half(v0);
                        aux[(size_t)m_hi * ldc + nn] = __float2half(v1);
                    }
                } else {
                    __half* C = (__half*)Cv;
                    C[(size_t)m_lo * ldc + nn] = __float2half(v0);
                    C[(size_t)m_hi * ldc + nn] = __float2half(v1);
                }
            }
        }
    }
}

// ======== scores + exp + row-partial-sums (fp16 mma), P unnormalized =========
__global__ __launch_bounds__(256, 2)
void scores_p_kernel(const __half* __restrict__ qkvH, __half* __restrict__ P,
                     float* __restrict__ psum) {
    int q = blockIdx.x, bh = blockIdx.z;
    int tb = 0;
    while ((tb + 1) * (tb + 2) / 2 <= q) tb++;
    int kb = q - tb * (tb + 1) / 2;
    int b = bh / Hh, h = bh % Hh;
    int k0 = kb * 128, t0 = tb * 128;

    __shared__ __align__(16) __half ssm[128 * 136];
    __shared__ float sums[128][2];

    int tid = threadIdx.x;
    int warp = tid >> 5, lane = tid & 31;
    int wm = warp & 3, wn = warp >> 2;
    int grp = lane >> 2, tig = lane & 3;
    int lr = lane & 7, sub = lane >> 3;

    uint32_t sb = smem_u32(ssm);
    uint32_t Ksb = sb, Qsb = sb + 16384u;
    const __half* Kb_ = qkvH + (size_t)(b * Tt + k0) * QKV_P + Cc + h * HSs;
    const __half* Qb_ = qkvH + (size_t)(b * Tt + t0) * QKV_P + h * HSs;

#pragma unroll
    for (int it = 0; it < 4; it++) {
        int slot = tid + it * 256;
        int r = slot >> 3, c = slot & 7;
        uint32_t so = (uint32_t)(r * 128 + ((c ^ (r & 7)) << 4));
        cp_async16(Ksb + so, Kb_ + (size_t)r * QKV_P + c * 8);
        cp_async16(Qsb + so, Qb_ + (size_t)r * QKV_P + c * 8);
    }
    cp_commit();
    cp_wait<0>();
    __syncthreads();

    float acc[2][8][4];
#pragma unroll
    for (int i = 0; i < 2; i++)
#pragma unroll
        for (int j = 0; j < 8; j++)
#pragma unroll
            for (int q2 = 0; q2 < 4; q2++) acc[i][j][q2] = 0.f;

    int rowA[2], rowB[4];
#pragma unroll
    for (int fm = 0; fm < 2; fm++) rowA[fm] = wm * 32 + fm * 16 + (sub & 1) * 8 + lr;
#pragma unroll
    for (int p = 0; p < 4; p++) rowB[p] = wn * 64 + p * 16 + (sub >> 1) * 8 + lr;
    int chA = sub >> 1, chB = sub & 1;

#pragma unroll
    for (int k16 = 0; k16 < 4; k16++) {
        int cb = k16 * 2;
        uint32_t afr[2][4];
#pragma unroll
        for (int fm = 0; fm < 2; fm++) {
            int r = rowA[fm];
            ldm_x4(afr[fm], Ksb + r * 128 + (((cb + chA) ^ (r & 7)) << 4));
        }
        uint32_t bfr[4][4];
#pragma unroll
        for (int p = 0; p < 4; p++) {
            int r = rowB[p];
            ldm_x4(bfr[p], Qsb + r * 128 + (((cb + chB) ^ (r & 7)) << 4));
        }
#pragma unroll
        for (int fm = 0; fm < 2; fm++)
#pragma unroll
            for (int fn = 0; fn < 8; fn++)
                mma_f16(acc[fm][fn], afr[fm], &bfr[fn >> 1][(fn & 1) * 2]);
    }
    __syncthreads();

    float rp[2][2] = {{0.f, 0.f}, {0.f, 0.f}};
#pragma unroll
    for (int fm = 0; fm < 2; fm++) {
        int kl = wm * 32 + fm * 16 + grp;
        int kh = kl + 8;
#pragma unroll
        for (int fn = 0; fn < 8; fn++) {
            int tc = wn * 64 + fn * 8 + tig * 2;
#pragma unroll
            for (int e = 0; e < 2; e++) {
                int t = tc + e;
                float v0 = (t0 + t >= k0 + kl) ? __expf(0.125f * acc[fm][fn][e]) : 0.f;
                float v1 = (t0 + t >= k0 + kh) ? __expf(0.125f * acc[fm][fn][e + 2]) : 0.f;
                ssm[kl * 136 + t] = __float2half(v0);
                ssm[kh * 136 + t] = __float2half(v1);
                rp[fm][0] += v0;
                rp[fm][1] += v1;
            }
        }
    }
#pragma unroll
    for (int fm = 0; fm < 2; fm++)
#pragma unroll
        for (int hl = 0; hl < 2; hl++) {
            rp[fm][hl] += __shfl_xor_sync(0xffffffffu, rp[fm][hl], 1);
            rp[fm][hl] += __shfl_xor_sync(0xffffffffu, rp[fm][hl], 2);
        }
    if (tig == 0) {
#pragma unroll
        for (int fm = 0; fm < 2; fm++) {
            sums[wm * 32 + fm * 16 + grp][wn]     = rp[fm][0];
            sums[wm * 32 + fm * 16 + grp + 8][wn] = rp[fm][1];
        }
    }
    __syncthreads();

    __half* Pb = P + ((size_t)bh * Tt + k0) * Tt + t0;
#pragma unroll
    for (int i = 0; i < 8; i++) {
        int idx = tid + i * 256;
        int r = idx >> 4, c = idx & 15;
        uint4 v = *reinterpret_cast<const uint4*>(&ssm[r * 136 + c * 8]);
        *reinterpret_cast<uint4*>(Pb + (size_t)r * Tt + c * 8) = v;
    }
    if (tid < 128)
        psum[((size_t)bh * 8 + tb) * Tt + k0 + tid] = sums[tid][0] + sums[tid][1];
}

// ---------------- PV via fp16 mma: double-buffered (race-fixed) ---------------
__global__ __launch_bounds__(256, 2)
void pv_fp16_kernel(const __half* __restrict__ P, const __half* __restrict__ qkvH,
                    const float* __restrict__ psum, __half* __restrict__ att) {
    int tb = blockIdx.x, bh = blockIdx.y;
    int b = bh / Hh, h = bh % Hh;
    int t0 = tb * 128;

    __shared__ __align__(16) __half Pt[2][64 * 128];  // [k][t] 256B rows
    __shared__ __align__(16) __half Vt[2][64 * 64];   // [s][k] 128B rows
    __shared__ float invs[1024];

    int tid = threadIdx.x;
    int warp = tid >> 5, lane = tid & 31;
    int wm = warp & 3, wn = warp >> 2;
    int grp = lane >> 2, tig = lane & 3;
    int lr = lane & 7, sub = lane >> 3;

    uint32_t Ptb0 = smem_u32(Pt[0]);

    int nk = 2 * (tb + 1);
    int Kext = nk * 64;
    for (int i = tid; i < Kext; i += 256) {
        int tb0 = i >> 7;
        float s = 0.f;
        for (int t2 = tb0; t2 < 8; t2++)
            s += psum[((size_t)bh * 8 + t2) * Tt + i];
        invs[i] = 1.f / s;
    }
    __syncthreads();  // invs ready for V writes

    auto issueP = [&](int kt, int buf) {
        const __half* Pg = P + ((size_t)bh * Tt + kt * 64) * Tt + t0;
        uint32_t base = Ptb0 + (uint32_t)buf * (64 * 128 * 2);
#pragma unroll
        for (int i = 0; i < 4; i++) {
            int idx = tid + i * 256;
            int r = idx >> 4, c = idx & 15;
            uint32_t so = (uint32_t)(r * 256 + ((c ^ (r & 7)) << 4));
            cp_async16(base + so, Pg + (size_t)r * Tt + c * 8);
        }
    };
    auto writeV = [&](int kt, int buf) {
        const __half* Vg = qkvH + (size_t)(b * Tt + kt * 64) * QKV_P + 2 * Cc + h * HSs;
        __half* Vb = Vt[buf];
        int k0 = kt * 64;
#pragma unroll
        for (int i = 0; i < 8; i++) {
            int idx = tid + i * 256;
            int kk = idx >> 5, sp = idx & 31;
            uint32_t v = *reinterpret_cast<const uint32_t*>(Vg + (size_t)kk * QKV_P + sp * 2);
            float iv = invs[k0 + kk];
            __half2 h2 = *(const __half2*)&v;
            __half s0 = __float2half(__half2float(h2.x) * iv);
            __half s1 = __float2half(__half2float(h2.y) * iv);
            int s_ = sp * 2;
            Vb[s_ * 64 + ((((kk >> 3) ^ (s_ & 7)) << 3) | (kk & 7))] = s0;
            s_++;
            Vb[s_ * 64 + ((((kk >> 3) ^ (s_ & 7)) << 3) | (kk & 7))] = s1;
        }
    };

    float acc[2][4][4];
#pragma unroll
    for (int i = 0; i < 2; i++)
#pragma unroll
        for (int j = 0; j < 4; j++)
#pragma unroll
            for (int q = 0; q < 4; q++) acc[i][j][q] = 0.f;

    int rowB[2];
#pragma unroll
    for (int p = 0; p < 2; p++) rowB[p] = wn * 32 + p * 16 + (sub >> 1) * 8 + lr;
    int chB = sub & 1;
    int tcolA = wm * 32 + (sub & 1) * 8;
    int krowA = (sub >> 1) * 8 + lr;

    // prologue: P(0) in flight, V(0) written
    issueP(0, 0);
    cp_commit();
    writeV(0, 0);

#pragma unroll 1
    for (int kt = 0; kt < nk; kt++) {
        int buf = kt & 1;
        cp_wait<0>();       // P(kt) landed (only group in flight)
        __syncthreads();    // V(kt) visible; all warps done computing on buf^1
        // NOW safe to refill buf^1 (every warp finished reading it)
        if (kt + 1 < nk) {
            issueP(kt + 1, buf ^ 1);
            cp_commit();
            writeV(kt + 1, buf ^ 1);
        }

        uint32_t Pbase = Ptb0 + (uint32_t)buf * (64 * 128 * 2);
        uint32_t Vbase = smem_u32(Vt[buf]);
#pragma unroll
        for (int k16 = 0; k16 < 4; k16++) {
            uint32_t afr[2][4];
#pragma unroll
            for (int fm = 0; fm < 2; fm++) {
                int krow = k16 * 16 + krowA;
                int tcol = tcolA + fm * 16;
                uint32_t addr = Pbase + krow * 256 + ((((tcol >> 3) ^ (krow & 7)) << 4));
                ldm_x4_trans(afr[fm], addr);
            }
            int cb = k16 * 2;
            uint32_t bfr[2][4];
#pragma unroll
            for (int p = 0; p < 2; p++) {
                int r = rowB[p];
                ldm_x4(bfr[p], Vbase + r * 128 + (((cb + chB) ^ (r & 7)) << 4));
            }
#pragma unroll
            for (int fm = 0; fm < 2; fm++)
#pragma unroll
                for (int fn = 0; fn < 4; fn++)
                    mma_f16(acc[fm][fn], afr[fm], &bfr[fn >> 1][(fn & 1) * 2]);
        }
    }

#pragma unroll
    for (int fm = 0; fm < 2; fm++) {
        int m_lo = t0 + wm * 32 + fm * 16 + grp;
        int m_hi = m_lo + 8;
#pragma unroll
        for (int fn = 0; fn < 4; fn++) {
            int s = wn * 32 + fn * 8 + tig * 2;
#pragma unroll
            for (int e = 0; e < 2; e++) {
                att[(size_t)(b * Tt + m_lo) * Cc + h * HSs + s + e] = __float2half(acc[fm][fn][e]);
                att[(size_t)(b * Tt + m_hi) * Cc + h * HSs + s + e] = __float2half(acc[fm][fn][e + 2]);
            }
        }
    }
}

// ========== 128x128 fp16 GEMM, 3-stage (LM head + QKV) =======================
constexpr int LM_NKT = Cc / 64;
constexpr int LM_STAGE = 32768;
constexpr int LM_SMEM = 3 * LM_STAGE;

template<int MODE>  // 0: fp32 out + Vv guard (LM head); 1: fp16 out (QKV)
__global__ __launch_bounds__(256, 2)
void g128_fp16_kernel(const __half* __restrict__ A, const __half* __restrict__ Bt,
                      const float* __restrict__ bias, void* __restrict__ Cv, int ldc) {
    extern __shared__ __half smh[];
    int tid = threadIdx.x;
    int warp = tid >> 5, lane = tid & 31;
    int wm = warp & 3, wn = warp >> 2;
    int grp = lane >> 2, tig = lane & 3;
    int lr = lane & 7, sub = lane >> 3;
    int m0 = blockIdx.x * 128, n0 = blockIdx.y * 128;
    const __half* Ab = A + (size_t)m0 * Cc;
    const __half* Bb = Bt + (size_t)n0 * Cc;

    uint32_t sbase = smem_u32(smh);

    auto issue = [&](int kt, int stage) {
        uint32_t as = sbase + stage * (uint32_t)LM_STAGE;
        uint32_t bs = as + 16384u;
#pragma unroll
        for (int it = 0; it < 4; it++) {
            int slot = tid + it * 256;
            int r = slot >> 3, c = slot & 7;
            uint32_t so = (uint32_t)(r * 128 + ((c ^ (r & 7)) << 4));
            cp_async16(as + so, Ab + (size_t)r * Cc + kt * 64 + c * 8);
            cp_async16(bs + so, Bb + (size_t)r * Cc + kt * 64 + c * 8);
        }
    };

    float acc[2][8][4];
#pragma unroll
    for (int i = 0; i < 2; i++)
#pragma unroll
        for (int j = 0; j < 8; j++)
#pragma unroll
            for (int q = 0; q < 4; q++) acc[i][j][q] = 0.f;

    int rowA[2], rowB[4];
#pragma unroll
    for (int fm = 0; fm < 2; fm++) rowA[fm] = wm * 32 + fm * 16 + (sub & 1) * 8 + lr;
#pragma unroll
    for (int p = 0; p < 4; p++) rowB[p] = wn * 64 + p * 16 + (sub >> 1) * 8 + lr;
    int chA = sub >> 1, chB = sub & 1;

    issue(0, 0); cp_commit();
    issue(1, 1); cp_commit();

    int stage = 0;
#pragma unroll 1
    for (int kt = 0; kt < LM_NKT; kt++) {
        if (kt + 1 < LM_NKT) { cp_wait<1>(); } else { cp_wait<0>(); }
        __syncthreads();
        if (kt + 2 < LM_NKT) {
            int ns = stage + 2; if (ns >= 3) ns -= 3;
            issue(kt + 2, ns);
            cp_commit();
        }
        uint32_t as = sbase + stage * (uint32_t)LM_STAGE;
        uint32_t bs = as + 16384u;
#pragma unroll
        for (int k16 = 0; k16 < 4; k16++) {
            int cb = k16 * 2;
            uint32_t afr[2][4];
#pragma unroll
            for (int fm = 0; fm < 2; fm++) {
                int r = rowA[fm];
                ldm_x4(afr[fm], as + r * 128 + (((cb + chA) ^ (r & 7)) << 4));
            }
            uint32_t bfr[4][4];
#pragma unroll
            for (int p = 0; p < 4; p++) {
                int r = rowB[p];
                ldm_x4(bfr[p], bs + r * 128 + (((cb + chB) ^ (r & 7)) << 4));
            }
#pragma unroll
            for (int fm = 0; fm < 2; fm++)
#pragma unroll
                for (int fn = 0; fn < 8; fn++)
                    mma_f16(acc[fm][fn], afr[fm], &bfr[fn >> 1][(fn & 1) * 2]);
        }
        if (++stage >= 3) stage = 0;
    }

#pragma unroll
    for (int fm = 0; fm < 2; fm++) {
        int m_lo = m0 + wm * 32 + fm * 16 + grp;
        int m_hi = m_lo + 8;
#pragma unroll
        for (int fn = 0; fn < 8; fn++) {
            int n = n0 + wn * 64 + fn * 8 + tig * 2;
#pragma unroll
            for (int e = 0; e < 2; e++) {
                int nn = n + e;
                if (MODE == 0 && nn >= Vv) continue;
                float bv = bias[nn];
                float v0 = acc[fm][fn][e]     + bv;
                float v1 = acc[fm][fn][e + 2] + bv;
                if constexpr (MODE == 0) {
                    float* C = (float*)Cv;
                    C[(size_t)m_lo * ldc + nn] = v0;
                    C[(size_t)m_hi * ldc + nn] = v1;
                } else {
                    __half* C = (__half*)Cv;
                    C[(size_t)m_lo * ldc + nn] = __float2half(v0);
                    C[(size_t)m_hi * ldc + nn] = __float2half(v1);
                }
            }
        }
    }
}

// ---------------- host launcher ---------------------------------------------
static float* symaddr(const void* s) {
    void* p = nullptr;
    cudaGetSymbolAddress(&p, s);
    return (float*)p;
}

extern "C" void kernel_launch(void* const* d_in, const int* in_sizes, int n_in,
                              void* d_out, int out_size) {
    const int*   x    = (const int*)d_in[0];
    const float* tok  = (const float*)d_in[1];
    const float* pos  = (const float*)d_in[2];
    const float* Wq   = (const float*)d_in[3];
    const float* bq   = (const float*)d_in[4];
    const float* Wk   = (const float*)d_in[5];
    const float* bk   = (const float*)d_in[6];
    const float* Wv   = (const float*)d_in[7];
    const float* bv   = (const float*)d_in[8];
    const float* Wo   = (const float*)d_in[9];
    const float* bo   = (const float*)d_in[10];
    const float* ln1g = (const float*)d_in[11];
    const float* ln1b = (const float*)d_in[12];
    const float* W1   = (const float*)d_in[13];
    const float* b1   = (const float*)d_in[14];
    const float* W2   = (const float*)d_in[15];
    const float* b2   = (const float*)d_in[16];
    const float* ln2g = (const float*)d_in[17];
    const float* ln2b = (const float*)d_in[18];
    const float* Wlm  = (const float*)d_in[19];
    const float* blm  = (const float*)d_in[20];
    float* out = (float*)d_out;

    float* ph      = symaddr(g_h);
    __half* paH    = (__half*)symaddr(g_aH);
    __half* pqkvH  = (__half*)symaddr(g_qkvH);
    __half* pattH  = (__half*)symaddr(g_attH);
    __half* pmH    = (__half*)symaddr(g_mH);
    __half* pP     = (__half*)symaddr(g_P);
    float* ppsum   = symaddr(g_psum);
    __half* pWqkvT = (__half*)symaddr(g_WqkvT);
    float* pbqkv   = symaddr(g_bqkv);
    __half* pWoT   = (__half*)symaddr(g_WoT);
    __half* pW1T   = (__half*)symaddr(g_W1T);
    __half* pW2T   = (__half*)symaddr(g_W2T);
    __half* phH    = (__half*)symaddr(g_hH);
    __half* pWlmH  = (__half*)symaddr(g_WlmH);

    static bool attr_done = false;
    if (!attr_done) {
        cudaFuncSetAttribute((const void*)h16_gemm_kernel<1>,  cudaFuncAttributeMaxDynamicSharedMemorySize, H16_SMEM);
        cudaFuncSetAttribute((const void*)h16_gemm_kernel<2>,  cudaFuncAttributeMaxDynamicSharedMemorySize, H16_SMEM);
        cudaFuncSetAttribute((const void*)h16_gemm_kernel<18>, cudaFuncAttributeMaxDynamicSharedMemorySize, H16_SMEM);
        cudaFuncSetAttribute((const void*)g128_fp16_kernel<0>, cudaFuncAttributeMaxDynamicSharedMemorySize, LM_SMEM);
        cudaFuncSetAttribute((const void*)g128_fp16_kernel<1>, cudaFuncAttributeMaxDynamicSharedMemorySize, LM_SMEM);
        attr_done = true;
    }

    // launch 0: embed + all weight prep
    prep_kernel<<<NB_WLM + NB_TRA + NB_QKV + NB_EMB, 256>>>(
        Wlm, pWlmH, Wo, W1, W2, pWoT, pW1T, pW2T,
        Wq, Wk, Wv, bq, bk, bv, pWqkvT, pbqkv,
        x, tok, pos, ph);

    dim3 g_qkv_grid(M_ROWS / 128, QKV_P / 128);   // (16, 9)
    dim3 g_c_grid(M_ROWS / 64, Cc / 128);         // (32, 3)

    for (int l = 0; l < NLl; l++) {
        ln_kernel<<<M_ROWS, 128>>>(ph, ln1g + l * Cc, ln1b + l * Cc, paH);

        g128_fp16_kernel<1><<<g_qkv_grid, 256, LM_SMEM>>>(
            paH, pWqkvT + (size_t)l * QKV_P * Cc, pbqkv + l * QKV_P, pqkvH, QKV_P);

        scores_p_kernel<<<dim3(36, 1, BH), 256>>>(pqkvH, pP, ppsum);
        pv_fp16_kernel<<<dim3(8, BH), 256>>>(pP, pqkvH, ppsum, pattH);

        h16_gemm_kernel<2><<<g_c_grid, 256, H16_SMEM>>>(
            pattH, pWoT + (size_t)l * Cc * Cc, bo + l * Cc, ph, nullptr, Cc);

        ln_kernel<<<M_ROWS, 128>>>(ph, ln2g + l * Cc, ln2b + l * Cc, paH);

        h16_gemm_kernel<1><<<g_c_grid, 256, H16_SMEM>>>(
            paH, pW1T + (size_t)l * Cc * Cc, b1 + l * Cc, pmH, nullptr, Cc);

        if (l == NLl - 1) {
            h16_gemm_kernel<18><<<g_c_grid, 256, H16_SMEM>>>(
                pmH, pW2T + (size_t)l * Cc * Cc, b2 + l * Cc, ph, phH, Cc);
        } else {
            h16_gemm_kernel<2><<<g_c_grid, 256, H16_SMEM>>>(
                pmH, pW2T + (size_t)l * Cc * Cc, b2 + l * Cc, ph, nullptr, Cc);
        }
    }

    // LM head (fp16 tensor cores, 3-stage pipeline, 128x128)
    g128_fp16_kernel<0><<<dim3(M_ROWS / 128, V_PAD / 128), 256, LM_SMEM>>>(
        phH, pWlmH, blm, out, Vv);
}

// round 17
// speedup vs baseline: 1.0190x; 1.0190x over previous
#include <cuda_runtime.h>
#include <cuda_fp16.h>
#include <cstdint>

// Problem constants
constexpr int Vv = 50257, Cc = 384, Tt = 1024, Hh = 6, HSs = 64, NLl = 3, Bb = 2;
constexpr int M_ROWS = Bb * Tt;   // 2048
constexpr int BH = Bb * Hh;       // 12
constexpr int V_PAD = 50304;      // 393 * 128
constexpr int QKV_P = 3 * Cc;     // 1152

// ---------------- scratch (__device__ globals; no allocation allowed) --------
__device__ float g_h[M_ROWS * Cc];
__device__ __half g_aH[M_ROWS * Cc];
__device__ __half g_qkvH[M_ROWS * QKV_P];
__device__ __half g_attH[M_ROWS * Cc];
__device__ __half g_mH[M_ROWS * Cc];
__device__ __half g_P[(size_t)BH * Tt * Tt];
__device__ float g_psum[BH * 8 * Tt];
__device__ __half g_WqkvT[NLl * QKV_P * Cc];
__device__ float g_bqkv[NLl * QKV_P];
__device__ __half g_WoT[NLl * Cc * Cc];
__device__ __half g_W1T[NLl * Cc * Cc];
__device__ __half g_W2T[NLl * Cc * Cc];
__device__ __half g_hH[M_ROWS * Cc];
__device__ __half g_WlmH[(size_t)V_PAD * Cc];

// ---------------- unified prep (weights + embedding, one launch) -------------
constexpr int NB_WLM = (V_PAD / 64) * (Cc / 64);
constexpr int NB_TRA = (Cc / 32) * (Cc / 32) * 3 * NLl;
constexpr int QKV_ELEMS = NLl * QKV_P * Cc + NLl * QKV_P;
constexpr int NB_QKV = (QKV_ELEMS + 255) / 256;
constexpr int NB_EMB = (M_ROWS * Cc + 255) / 256;

__global__ __launch_bounds__(256)
void prep_kernel(const float* __restrict__ Wlm, __half* __restrict__ Bt,
                 const float* __restrict__ Wo, const float* __restrict__ W1,
                 const float* __restrict__ W2,
                 __half* __restrict__ To, __half* __restrict__ T1, __half* __restrict__ T2,
                 const float* __restrict__ Wq, const float* __restrict__ Wk,
                 const float* __restrict__ Wv,
                 const float* __restrict__ bq, const float* __restrict__ bk,
                 const float* __restrict__ bv,
                 __half* __restrict__ OW, float* __restrict__ OB,
                 const int* __restrict__ x, const float* __restrict__ tok,
                 const float* __restrict__ pos, float* __restrict__ h) {
    __shared__ float tile[64 * 65];
    int bid = blockIdx.x;
    int tid = threadIdx.x;

    if (bid < NB_WLM) {
        int n0 = (bid % (V_PAD / 64)) * 64, k0 = (bid / (V_PAD / 64)) * 64;
#pragma unroll
        for (int it = 0; it < 16; it++) {
            int idx = tid + it * 256;
            int r = idx >> 6, c = idx & 63;
            int n = n0 + c;
            tile[r * 65 + c] = (n < Vv) ? Wlm[(size_t)(k0 + r) * Vv + n] : 0.f;
        }
        __syncthreads();
#pragma unroll
        for (int it = 0; it < 2; it++) {
            int idx = tid + it * 256;
            int n = idx >> 3, kc = idx & 7;
            __half hv[8];
#pragma unroll
            for (int j = 0; j < 8; j++) hv[j] = __float2half(tile[(kc * 8 + j) * 65 + n]);
            *reinterpret_cast<uint4*>(Bt + (size_t)(n0 + n) * Cc + k0 + kc * 8) =
                *reinterpret_cast<const uint4*>(hv);
        }
    } else if (bid < NB_WLM + NB_TRA) {
        int id = bid - NB_WLM;
        int id2 = id % 144;
        int xt = id2 % 12, yt = id2 / 12;
        int z = id / 144;
        int wi = z % 3, l = z / 3;
        const float* W = ((wi == 0) ? Wo : (wi == 1) ? W1 : W2) + (size_t)l * Cc * Cc;
        __half* T = ((wi == 0) ? To : (wi == 1) ? T1 : T2) + (size_t)l * Cc * Cc;
        int n0 = xt * 32, k0 = yt * 32;
        int tx = tid & 31, ty = tid >> 5;
        for (int dy = ty; dy < 32; dy += 8)
            tile[dy * 33 + tx] = W[(size_t)(k0 + dy) * Cc + n0 + tx];
        __syncthreads();
        for (int dy = ty; dy < 32; dy += 8)
            T[(size_t)(n0 + dy) * Cc + k0 + tx] = __float2half(tile[tx * 33 + dy]);
    } else if (bid < NB_WLM + NB_TRA + NB_QKV) {
        int i = (bid - NB_WLM - NB_TRA) * 256 + tid;
        int total_w = NLl * QKV_P * Cc;
        if (i < total_w) {
            int k = i % Cc;
            int n = (i / Cc) % QKV_P;
            int l = i / (Cc * QKV_P);
            int sel = n / Cc, hh = (n % Cc) / HSs, s = n % HSs;
            const float* W = (sel == 0) ? Wq : (sel == 1) ? Wk : Wv;
            OW[i] = __float2half(W[(((size_t)l * Hh + hh) * Cc + k) * HSs + s]);
        } else {
            int j = i - total_w;
            if (j < NLl * QKV_P) {
                int n = j % QKV_P, l = j / QKV_P;
                int sel = n / Cc, hh = (n % Cc) / HSs, s = n % HSs;
                const float* B = (sel == 0) ? bq : (sel == 1) ? bk : bv;
                OB[j] = B[((size_t)l * Hh + hh) * HSs + s];
            }
        }
    } else {
        int i = (bid - NB_WLM - NB_TRA - NB_QKV) * 256 + tid;
        if (i < M_ROWS * Cc) {
            int row = i / Cc, c = i % Cc;
            int t = row % Tt;
            h[i] = tok[(size_t)x[row] * Cc + c] + pos[t * Cc + c];
        }
    }
}

// ---------------- layernorm (vectorized, fp16 out) ---------------------------
__global__ void ln_kernel(const float* __restrict__ x, const float* __restrict__ g,
                          const float* __restrict__ b, __half* __restrict__ y) {
    int row = blockIdx.x;
    const float4* xr4 = reinterpret_cast<const float4*>(x + (size_t)row * Cc);
    float4 v = make_float4(0.f, 0.f, 0.f, 0.f);
    int tid = threadIdx.x;
    if (tid < 96) v = xr4[tid];
    float lsum = v.x + v.y + v.z + v.w;
    float lsq = v.x * v.x + v.y * v.y + v.z * v.z + v.w * v.w;
    __shared__ float sh[64];
    int lane = tid & 31, wid = tid >> 5;
#pragma unroll
    for (int o = 16; o; o >>= 1) {
        lsum += __shfl_xor_sync(0xffffffffu, lsum, o);
        lsq  += __shfl_xor_sync(0xffffffffu, lsq,  o);
    }
    if (lane == 0) { sh[wid] = lsum; sh[wid + 32] = lsq; }
    __syncthreads();
    if (tid == 0) {
        float s = 0.f, q = 0.f;
        for (int w = 0; w < 4; w++) { s += sh[w]; q += sh[w + 32]; }
        sh[0] = s; sh[32] = q;
    }
    __syncthreads();
    float mu = sh[0] / Cc;
    float var = sh[32] / Cc - mu * mu;
    float rstd = rsqrtf(var + 1e-5f);
    if (tid < 96) {
        const float4 g4 = reinterpret_cast<const float4*>(g)[tid];
        const float4 b4 = reinterpret_cast<const float4*>(b)[tid];
        __half2 o0 = __floats2half2_rn((v.x - mu) * rstd * g4.x + b4.x,
                                       (v.y - mu) * rstd * g4.y + b4.y);
        __half2 o1 = __floats2half2_rn((v.z - mu) * rstd * g4.z + b4.z,
                                       (v.w - mu) * rstd * g4.w + b4.w);
        uint2 pack;
        pack.x = *reinterpret_cast<uint32_t*>(&o0);
        pack.y = *reinterpret_cast<uint32_t*>(&o1);
        reinterpret_cast<uint2*>(y + (size_t)row * Cc)[tid] = pack;
    }
}

// ---------------- common asm helpers ----------------------------------------
__device__ __forceinline__ uint32_t smem_u32(const void* p) {
    uint32_t a;
    asm("{ .reg .u64 t; cvta.to.shared.u64 t, %1; cvt.u32.u64 %0, t; }" : "=r"(a) : "l"(p));
    return a;
}
__device__ __forceinline__ void cp_async16(uint32_t saddr, const void* g) {
    asm volatile("cp.async.cg.shared.global [%0], [%1], 16;" :: "r"(saddr), "l"(g) : "memory");
}
__device__ __forceinline__ void cp_commit() {
    asm volatile("cp.async.commit_group;" ::: "memory");
}
template<int N>
__device__ __forceinline__ void cp_wait() {
    asm volatile("cp.async.wait_group %0;" :: "n"(N) : "memory");
}
__device__ __forceinline__ void ldm_x4(uint32_t* r, uint32_t addr) {
    asm volatile("ldmatrix.sync.aligned.m8n8.x4.shared.b16 {%0,%1,%2,%3}, [%4];"
                 : "=r"(r[0]), "=r"(r[1]), "=r"(r[2]), "=r"(r[3]) : "r"(addr));
}
__device__ __forceinline__ void ldm_x4_trans(uint32_t* r, uint32_t addr) {
    asm volatile("ldmatrix.sync.aligned.m8n8.x4.trans.shared.b16 {%0,%1,%2,%3}, [%4];"
                 : "=r"(r[0]), "=r"(r[1]), "=r"(r[2]), "=r"(r[3]) : "r"(addr));
}
__device__ __forceinline__ void mma_f16(float* c, const uint32_t* a, const uint32_t* b) {
    asm volatile(
        "mma.sync.aligned.m16n8k16.row.col.f32.f16.f16.f32 "
        "{%0,%1,%2,%3}, {%4,%5,%6,%7}, {%8,%9}, {%0,%1,%2,%3};"
        : "+f"(c[0]), "+f"(c[1]), "+f"(c[2]), "+f"(c[3])
        : "r"(a[0]), "r"(a[1]), "r"(a[2]), "r"(a[3]), "r"(b[0]), "r"(b[1]));
}

// ================= fp16 layer GEMM: CTA 64x128, K-tile 64, 3-stage ===========
constexpr int H16_NKT = Cc / 64;
constexpr int H16_STAGE = 24576;
constexpr int H16_SMEM = 3 * H16_STAGE;

template<int FLAGS>  // 1=relu, 2=accumulate fp32, 16=also fp16 aux copy
__global__ __launch_bounds__(256, 2)
void h16_gemm_kernel(const __half* __restrict__ A, const __half* __restrict__ Bt,
                     const float* __restrict__ bias, void* __restrict__ Cv,
                     __half* __restrict__ aux, int ldc) {
    extern __shared__ __half smh[];
    int tid = threadIdx.x;
    int warp = tid >> 5, lane = tid & 31;
    int wm = warp & 1, wn = warp >> 1;
    int grp = lane >> 2, tig = lane & 3;
    int lr = lane & 7, sub = lane >> 3;
    int m0 = blockIdx.x * 64, n0 = blockIdx.y * 128;
    const __half* Ab = A + (size_t)m0 * Cc;
    const __half* Bb = Bt + (size_t)n0 * Cc;
    uint32_t sbase = smem_u32(smh);

    auto issue = [&](int kt, int stage) {
        uint32_t as = sbase + stage * (uint32_t)H16_STAGE;
        uint32_t bs = as + 8192u;
#pragma unroll
        for (int it = 0; it < 2; it++) {
            int slot = tid + it * 256;
            int r = slot >> 3, c = slot & 7;
            uint32_t so = (uint32_t)(r * 128 + ((c ^ (r & 7)) << 4));
            cp_async16(as + so, Ab + (size_t)r * Cc + kt * 64 + c * 8);
        }
#pragma unroll
        for (int it = 0; it < 4; it++) {
            int slot = tid + it * 256;
            int r = slot >> 3, c = slot & 7;
            uint32_t so = (uint32_t)(r * 128 + ((c ^ (r & 7)) << 4));
            cp_async16(bs + so, Bb + (size_t)r * Cc + kt * 64 + c * 8);
        }
    };

    float acc[2][4][4];
#pragma unroll
    for (int i = 0; i < 2; i++)
#pragma unroll
        for (int j = 0; j < 4; j++)
#pragma unroll
            for (int q = 0; q < 4; q++) acc[i][j][q] = 0.f;

    int rowA[2], rowB[2];
#pragma unroll
    for (int fm = 0; fm < 2; fm++) rowA[fm] = wm * 32 + fm * 16 + (sub & 1) * 8 + lr;
#pragma unroll
    for (int p = 0; p < 2; p++) rowB[p] = wn * 32 + p * 16 + (sub >> 1) * 8 + lr;
    int chA = sub >> 1, chB = sub & 1;

    issue(0, 0); cp_commit();
    issue(1, 1); cp_commit();

    int stage = 0;
#pragma unroll 1
    for (int kt = 0; kt < H16_NKT; kt++) {
        if (kt + 1 < H16_NKT) { cp_wait<1>(); } else { cp_wait<0>(); }
        __syncthreads();
        if (kt + 2 < H16_NKT) {
            int ns = stage + 2; if (ns >= 3) ns -= 3;
            issue(kt + 2, ns);
            cp_commit();
        }
        uint32_t as = sbase + stage * (uint32_t)H16_STAGE;
        uint32_t bs = as + 8192u;
#pragma unroll
        for (int k16 = 0; k16 < 4; k16++) {
            int cb = k16 * 2;
            uint32_t afr[2][4];
#pragma unroll
            for (int fm = 0; fm < 2; fm++) {
                int r = rowA[fm];
                ldm_x4(afr[fm], as + r * 128 + (((cb + chA) ^ (r & 7)) << 4));
            }
            uint32_t bfr[2][4];
#pragma unroll
            for (int p = 0; p < 2; p++) {
                int r = rowB[p];
                ldm_x4(bfr[p], bs + r * 128 + (((cb + chB) ^ (r & 7)) << 4));
            }
#pragma unroll
            for (int fm = 0; fm < 2; fm++)
#pragma unroll
                for (int fn = 0; fn < 4; fn++)
                    mma_f16(acc[fm][fn], afr[fm], &bfr[fn >> 1][(fn & 1) * 2]);
        }
        if (++stage >= 3) stage = 0;
    }

#pragma unroll
    for (int fm = 0; fm < 2; fm++) {
        int m_lo = m0 + wm * 32 + fm * 16 + grp;
        int m_hi = m_lo + 8;
#pragma unroll
        for (int fn = 0; fn < 4; fn++) {
            int n = n0 + wn * 32 + fn * 8 + tig * 2;
#pragma unroll
            for (int e = 0; e < 2; e++) {
                int nn = n + e;
                float bv = bias[nn];
                float v0 = acc[fm][fn][e]     + bv;
                float v1 = acc[fm][fn][e + 2] + bv;
                if (FLAGS & 1) { v0 = fmaxf(v0, 0.f); v1 = fmaxf(v1, 0.f); }
                if constexpr ((FLAGS & 2) != 0) {
                    float* C = (float*)Cv;
                    v0 += C[(size_t)m_lo * ldc + nn];
                    v1 += C[(size_t)m_hi * ldc + nn];
                    C[(size_t)m_lo * ldc + nn] = v0;
                    C[(size_t)m_hi * ldc + nn] = v1;
                    if constexpr ((FLAGS & 16) != 0) {
                        aux[(size_t)m_lo * ldc + nn] = __float2half(v0);
                        aux[(size_t)m_hi * ldc + nn] = __float2half(v1);
                    }
                } else {
                    __half* C = (__half*)Cv;
                    C[(size_t)m_lo * ldc + nn] = __float2half(v0);
                    C[(size_t)m_hi * ldc + nn] = __float2half(v1);
                }
            }
        }
    }
}

// ======== scores + exp + row-partial-sums (fp16 mma), P unnormalized =========
__global__ __launch_bounds__(256, 2)
void scores_p_kernel(const __half* __restrict__ qkvH, __half* __restrict__ P,
                     float* __restrict__ psum) {
    int q = blockIdx.x, bh = blockIdx.z;
    int tb = 0;
    while ((tb + 1) * (tb + 2) / 2 <= q) tb++;
    int kb = q - tb * (tb + 1) / 2;
    int b = bh / Hh, h = bh % Hh;
    int k0 = kb * 128, t0 = tb * 128;

    __shared__ __align__(16) __half ssm[128 * 136];
    __shared__ float sums[128][2];

    int tid = threadIdx.x;
    int warp = tid >> 5, lane = tid & 31;
    int wm = warp & 3, wn = warp >> 2;
    int grp = lane >> 2, tig = lane & 3;
    int lr = lane & 7, sub = lane >> 3;

    uint32_t sb = smem_u32(ssm);
    uint32_t Ksb = sb, Qsb = sb + 16384u;
    const __half* Kb_ = qkvH + (size_t)(b * Tt + k0) * QKV_P + Cc + h * HSs;
    const __half* Qb_ = qkvH + (size_t)(b * Tt + t0) * QKV_P + h * HSs;

#pragma unroll
    for (int it = 0; it < 4; it++) {
        int slot = tid + it * 256;
        int r = slot >> 3, c = slot & 7;
        uint32_t so = (uint32_t)(r * 128 + ((c ^ (r & 7)) << 4));
        cp_async16(Ksb + so, Kb_ + (size_t)r * QKV_P + c * 8);
        cp_async16(Qsb + so, Qb_ + (size_t)r * QKV_P + c * 8);
    }
    cp_commit();
    cp_wait<0>();
    __syncthreads();

    float acc[2][8][4];
#pragma unroll
    for (int i = 0; i < 2; i++)
#pragma unroll
        for (int j = 0; j < 8; j++)
#pragma unroll
            for (int q2 = 0; q2 < 4; q2++) acc[i][j][q2] = 0.f;

    int rowA[2], rowB[4];
#pragma unroll
    for (int fm = 0; fm < 2; fm++) rowA[fm] = wm * 32 + fm * 16 + (sub & 1) * 8 + lr;
#pragma unroll
    for (int p = 0; p < 4; p++) rowB[p] = wn * 64 + p * 16 + (sub >> 1) * 8 + lr;
    int chA = sub >> 1, chB = sub & 1;

#pragma unroll
    for (int k16 = 0; k16 < 4; k16++) {
        int cb = k16 * 2;
        uint32_t afr[2][4];
#pragma unroll
        for (int fm = 0; fm < 2; fm++) {
            int r = rowA[fm];
            ldm_x4(afr[fm], Ksb + r * 128 + (((cb + chA) ^ (r & 7)) << 4));
        }
        uint32_t bfr[4][4];
#pragma unroll
        for (int p = 0; p < 4; p++) {
            int r = rowB[p];
            ldm_x4(bfr[p], Qsb + r * 128 + (((cb + chB) ^ (r & 7)) << 4));
        }
#pragma unroll
        for (int fm = 0; fm < 2; fm++)
#pragma unroll
            for (int fn = 0; fn < 8; fn++)
                mma_f16(acc[fm][fn], afr[fm], &bfr[fn >> 1][(fn & 1) * 2]);
    }
    __syncthreads();

    // epilogue: exp, packed half2 stores, row partials
    float rp[2][2] = {{0.f, 0.f}, {0.f, 0.f}};
#pragma unroll
    for (int fm = 0; fm < 2; fm++) {
        int kl = wm * 32 + fm * 16 + grp;
        int kh = kl + 8;
        int dl = t0 - k0 - kl;   // t + dl >= 0 means valid for row kl
        int dh = t0 - k0 - kh;
#pragma unroll
        for (int fn = 0; fn < 8; fn++) {
            int tc = wn * 64 + fn * 8 + tig * 2;
            float v00 = (tc + dl >= 0)     ? __expf(0.125f * acc[fm][fn][0]) : 0.f;
            float v01 = (tc + 1 + dl >= 0) ? __expf(0.125f * acc[fm][fn][1]) : 0.f;
            float v10 = (tc + dh >= 0)     ? __expf(0.125f * acc[fm][fn][2]) : 0.f;
            float v11 = (tc + 1 + dh >= 0) ? __expf(0.125f * acc[fm][fn][3]) : 0.f;
            *reinterpret_cast<__half2*>(&ssm[kl * 136 + tc]) = __floats2half2_rn(v00, v01);
            *reinterpret_cast<__half2*>(&ssm[kh * 136 + tc]) = __floats2half2_rn(v10, v11);
            rp[fm][0] += v00 + v01;
            rp[fm][1] += v10 + v11;
        }
    }
#pragma unroll
    for (int fm = 0; fm < 2; fm++)
#pragma unroll
        for (int hl = 0; hl < 2; hl++) {
            rp[fm][hl] += __shfl_xor_sync(0xffffffffu, rp[fm][hl], 1);
            rp[fm][hl] += __shfl_xor_sync(0xffffffffu, rp[fm][hl], 2);
        }
    if (tig == 0) {
#pragma unroll
        for (int fm = 0; fm < 2; fm++) {
            sums[wm * 32 + fm * 16 + grp][wn]     = rp[fm][0];
            sums[wm * 32 + fm * 16 + grp + 8][wn] = rp[fm][1];
        }
    }
    __syncthreads();

    __half* Pb = P + ((size_t)bh * Tt + k0) * Tt + t0;
#pragma unroll
    for (int i = 0; i < 8; i++) {
        int idx = tid + i * 256;
        int r = idx >> 4, c = idx & 15;
        uint4 v = *reinterpret_cast<const uint4*>(&ssm[r * 136 + c * 8]);
        *reinterpret_cast<uint4*>(Pb + (size_t)r * Tt + c * 8) = v;
    }
    if (tid < 128)
        psum[((size_t)bh * 8 + tb) * Tt + k0 + tid] = sums[tid][0] + sums[tid][1];
}

// ---------------- PV via fp16 mma (serial, known-good) ------------------------
__global__ __launch_bounds__(256, 2)
void pv_fp16_kernel(const __half* __restrict__ P, const __half* __restrict__ qkvH,
                    const float* __restrict__ psum, __half* __restrict__ att) {
    int tb = blockIdx.x, bh = blockIdx.y;
    int b = bh / Hh, h = bh % Hh;
    int t0 = tb * 128;

    __shared__ __align__(16) __half Pt[64 * 128];  // [k][t] 256B rows
    __shared__ __align__(16) __half Vt[64 * 64];   // [s][k] 128B rows
    __shared__ float invs[1024];

    int tid = threadIdx.x;
    int warp = tid >> 5, lane = tid & 31;
    int wm = warp & 3, wn = warp >> 2;
    int grp = lane >> 2, tig = lane & 3;
    int lr = lane & 7, sub = lane >> 3;

    uint32_t Ptb = smem_u32(Pt), Vtb = smem_u32(Vt);

    int nk = 2 * (tb + 1);
    int Kext = nk * 64;
    for (int i = tid; i < Kext; i += 256) {
        int tb0 = i >> 7;
        float s = 0.f;
        for (int t2 = tb0; t2 < 8; t2++)
            s += psum[((size_t)bh * 8 + t2) * Tt + i];
        invs[i] = 1.f / s;
    }

    float acc[2][4][4];
#pragma unroll
    for (int i = 0; i < 2; i++)
#pragma unroll
        for (int j = 0; j < 4; j++)
#pragma unroll
            for (int q = 0; q < 4; q++) acc[i][j][q] = 0.f;

    int rowB[2];
#pragma unroll
    for (int p = 0; p < 2; p++) rowB[p] = wn * 32 + p * 16 + (sub >> 1) * 8 + lr;
    int chB = sub & 1;
    int tcolA = wm * 32 + (sub & 1) * 8;
    int krowA = (sub >> 1) * 8 + lr;

#pragma unroll 1
    for (int kt = 0; kt < nk; kt++) {
        int k0 = kt * 64;
        __syncthreads();
        const __half* Pg = P + ((size_t)bh * Tt + k0) * Tt + t0;
#pragma unroll
        for (int i = 0; i < 4; i++) {
            int idx = tid + i * 256;
            int r = idx >> 4, c = idx & 15;
            uint32_t so = (uint32_t)(r * 256 + ((c ^ (r & 7)) << 4));
            cp_async16(Ptb + so, Pg + (size_t)r * Tt + c * 8);
        }
        cp_commit();
        const __half* Vg = qkvH + (size_t)(b * Tt + k0) * QKV_P + 2 * Cc + h * HSs;
#pragma unroll
        for (int i = 0; i < 8; i++) {
            int idx = tid + i * 256;
            int kk = idx >> 5, sp = idx & 31;
            uint32_t v = *reinterpret_cast<const uint32_t*>(Vg + (size_t)kk * QKV_P + sp * 2);
            float iv = invs[k0 + kk];
            __half2 h2 = *(const __half2*)&v;
            __half s0 = __float2half(__half2float(h2.x) * iv);
            __half s1 = __float2half(__half2float(h2.y) * iv);
            int s_ = sp * 2;
            Vt[s_ * 64 + ((((kk >> 3) ^ (s_ & 7)) << 3) | (kk & 7))] = s0;
            s_++;
            Vt[s_ * 64 + ((((kk >> 3) ^ (s_ & 7)) << 3) | (kk & 7))] = s1;
        }
        cp_wait<0>();
        __syncthreads();
#pragma unroll
        for (int k16 = 0; k16 < 4; k16++) {
            uint32_t afr[2][4];
#pragma unroll
            for (int fm = 0; fm < 2; fm++) {
                int krow = k16 * 16 + krowA;
                int tcol = tcolA + fm * 16;
                uint32_t addr = Ptb + krow * 256 + ((((tcol >> 3) ^ (krow & 7)) << 4));
                ldm_x4_trans(afr[fm], addr);
            }
            int cb = k16 * 2;
            uint32_t bfr[2][4];
#pragma unroll
            for (int p = 0; p < 2; p++) {
                int r = rowB[p];
                ldm_x4(bfr[p], Vtb + r * 128 + (((cb + chB) ^ (r & 7)) << 4));
            }
#pragma unroll
            for (int fm = 0; fm < 2; fm++)
#pragma unroll
                for (int fn = 0; fn < 4; fn++)
                    mma_f16(acc[fm][fn], afr[fm], &bfr[fn >> 1][(fn & 1) * 2]);
        }
    }

#pragma unroll
    for (int fm = 0; fm < 2; fm++) {
        int m_lo = t0 + wm * 32 + fm * 16 + grp;
        int m_hi = m_lo + 8;
#pragma unroll
        for (int fn = 0; fn < 4; fn++) {
            int s = wn * 32 + fn * 8 + tig * 2;
#pragma unroll
            for (int e = 0; e < 2; e++) {
                att[(size_t)(b * Tt + m_lo) * Cc + h * HSs + s + e] = __float2half(acc[fm][fn][e]);
                att[(size_t)(b * Tt + m_hi) * Cc + h * HSs + s + e] = __float2half(acc[fm][fn][e + 2]);
            }
        }
    }
}

// ========== 128x128 fp16 GEMM, 3-stage (LM head + QKV) =======================
constexpr int LM_NKT = Cc / 64;
constexpr int LM_STAGE = 32768;
constexpr int LM_SMEM = 3 * LM_STAGE;

template<int MODE>  // 0: fp32 out + Vv guard (LM head); 1: fp16 out (QKV)
__global__ __launch_bounds__(256, 2)
void g128_fp16_kernel(const __half* __restrict__ A, const __half* __restrict__ Bt,
                      const float* __restrict__ bias, void* __restrict__ Cv, int ldc) {
    extern __shared__ __half smh[];
    int tid = threadIdx.x;
    int warp = tid >> 5, lane = tid & 31;
    int wm = warp & 3, wn = warp >> 2;
    int grp = lane >> 2, tig = lane & 3;
    int lr = lane & 7, sub = lane >> 3;
    int m0 = blockIdx.x * 128, n0 = blockIdx.y * 128;
    const __half* Ab = A + (size_t)m0 * Cc;
    const __half* Bb = Bt + (size_t)n0 * Cc;

    uint32_t sbase = smem_u32(smh);

    auto issue = [&](int kt, int stage) {
        uint32_t as = sbase + stage * (uint32_t)LM_STAGE;
        uint32_t bs = as + 16384u;
#pragma unroll
        for (int it = 0; it < 4; it++) {
            int slot = tid + it * 256;
            int r = slot >> 3, c = slot & 7;
            uint32_t so = (uint32_t)(r * 128 + ((c ^ (r & 7)) << 4));
            cp_async16(as + so, Ab + (size_t)r * Cc + kt * 64 + c * 8);
            cp_async16(bs + so, Bb + (size_t)r * Cc + kt * 64 + c * 8);
        }
    };

    float acc[2][8][4];
#pragma unroll
    for (int i = 0; i < 2; i++)
#pragma unroll
        for (int j = 0; j < 8; j++)
#pragma unroll
            for (int q = 0; q < 4; q++) acc[i][j][q] = 0.f;

    int rowA[2], rowB[4];
#pragma unroll
    for (int fm = 0; fm < 2; fm++) rowA[fm] = wm * 32 + fm * 16 + (sub & 1) * 8 + lr;
#pragma unroll
    for (int p = 0; p < 4; p++) rowB[p] = wn * 64 + p * 16 + (sub >> 1) * 8 + lr;
    int chA = sub >> 1, chB = sub & 1;

    issue(0, 0); cp_commit();
    issue(1, 1); cp_commit();

    int stage = 0;
#pragma unroll 1
    for (int kt = 0; kt < LM_NKT; kt++) {
        if (kt + 1 < LM_NKT) { cp_wait<1>(); } else { cp_wait<0>(); }
        __syncthreads();
        if (kt + 2 < LM_NKT) {
            int ns = stage + 2; if (ns >= 3) ns -= 3;
            issue(kt + 2, ns);
            cp_commit();
        }
        uint32_t as = sbase + stage * (uint32_t)LM_STAGE;
        uint32_t bs = as + 16384u;
#pragma unroll
        for (int k16 = 0; k16 < 4; k16++) {
            int cb = k16 * 2;
            uint32_t afr[2][4];
#pragma unroll
            for (int fm = 0; fm < 2; fm++) {
                int r = rowA[fm];
                ldm_x4(afr[fm], as + r * 128 + (((cb + chA) ^ (r & 7)) << 4));
            }
            uint32_t bfr[4][4];
#pragma unroll
            for (int p = 0; p < 4; p++) {
                int r = rowB[p];
                ldm_x4(bfr[p], bs + r * 128 + (((cb + chB) ^ (r & 7)) << 4));
            }
#pragma unroll
            for (int fm = 0; fm < 2; fm++)
#pragma unroll
                for (int fn = 0; fn < 8; fn++)
                    mma_f16(acc[fm][fn], afr[fm], &bfr[fn >> 1][(fn & 1) * 2]);
        }
        if (++stage >= 3) stage = 0;
    }

#pragma unroll
    for (int fm = 0; fm < 2; fm++) {
        int m_lo = m0 + wm * 32 + fm * 16 + grp;
        int m_hi = m_lo + 8;
#pragma unroll
        for (int fn = 0; fn < 8; fn++) {
            int n = n0 + wn * 64 + fn * 8 + tig * 2;
#pragma unroll
            for (int e = 0; e < 2; e++) {
                int nn = n + e;
                if (MODE == 0 && nn >= Vv) continue;
                float bv = bias[nn];
                float v0 = acc[fm][fn][e]     + bv;
                float v1 = acc[fm][fn][e + 2] + bv;
                if constexpr (MODE == 0) {
                    float* C = (float*)Cv;
                    C[(size_t)m_lo * ldc + nn] = v0;
                    C[(size_t)m_hi * ldc + nn] = v1;
                } else {
                    __half* C = (__half*)Cv;
                    C[(size_t)m_lo * ldc + nn] = __float2half(v0);
                    C[(size_t)m_hi * ldc + nn] = __float2half(v1);
                }
            }
        }
    }
}

// ---------------- host launcher ---------------------------------------------
static float* symaddr(const void* s) {
    void* p = nullptr;
    cudaGetSymbolAddress(&p, s);
    return (float*)p;
}

extern "C" void kernel_launch(void* const* d_in, const int* in_sizes, int n_in,
                              void* d_out, int out_size) {
    const int*   x    = (const int*)d_in[0];
    const float* tok  = (const float*)d_in[1];
    const float* pos  = (const float*)d_in[2];
    const float* Wq   = (const float*)d_in[3];
    const float* bq   = (const float*)d_in[4];
    const float* Wk   = (const float*)d_in[5];
    const float* bk   = (const float*)d_in[6];
    const float* Wv   = (const float*)d_in[7];
    const float* bv   = (const float*)d_in[8];
    const float* Wo   = (const float*)d_in[9];
    const float* bo   = (const float*)d_in[10];
    const float* ln1g = (const float*)d_in[11];
    const float* ln1b = (const float*)d_in[12];
    const float* W1   = (const float*)d_in[13];
    const float* b1   = (const float*)d_in[14];
    const float* W2   = (const float*)d_in[15];
    const float* b2   = (const float*)d_in[16];
    const float* ln2g = (const float*)d_in[17];
    const float* ln2b = (const float*)d_in[18];
    const float* Wlm  = (const float*)d_in[19];
    const float* blm  = (const float*)d_in[20];
    float* out = (float*)d_out;

    float* ph      = symaddr(g_h);
    __half* paH    = (__half*)symaddr(g_aH);
    __half* pqkvH  = (__half*)symaddr(g_qkvH);
    __half* pattH  = (__half*)symaddr(g_attH);
    __half* pmH    = (__half*)symaddr(g_mH);
    __half* pP     = (__half*)symaddr(g_P);
    float* ppsum   = symaddr(g_psum);
    __half* pWqkvT = (__half*)symaddr(g_WqkvT);
    float* pbqkv   = symaddr(g_bqkv);
    __half* pWoT   = (__half*)symaddr(g_WoT);
    __half* pW1T   = (__half*)symaddr(g_W1T);
    __half* pW2T   = (__half*)symaddr(g_W2T);
    __half* phH    = (__half*)symaddr(g_hH);
    __half* pWlmH  = (__half*)symaddr(g_WlmH);

    static bool attr_done = false;
    if (!attr_done) {
        cudaFuncSetAttribute((const void*)h16_gemm_kernel<1>,  cudaFuncAttributeMaxDynamicSharedMemorySize, H16_SMEM);
        cudaFuncSetAttribute((const void*)h16_gemm_kernel<2>,  cudaFuncAttributeMaxDynamicSharedMemorySize, H16_SMEM);
        cudaFuncSetAttribute((const void*)h16_gemm_kernel<18>, cudaFuncAttributeMaxDynamicSharedMemorySize, H16_SMEM);
        cudaFuncSetAttribute((const void*)g128_fp16_kernel<0>, cudaFuncAttributeMaxDynamicSharedMemorySize, LM_SMEM);
        cudaFuncSetAttribute((const void*)g128_fp16_kernel<1>, cudaFuncAttributeMaxDynamicSharedMemorySize, LM_SMEM);
        attr_done = true;
    }

    // launch 0: embed + all weight prep
    prep_kernel<<<NB_WLM + NB_TRA + NB_QKV + NB_EMB, 256>>>(
        Wlm, pWlmH, Wo, W1, W2, pWoT, pW1T, pW2T,
        Wq, Wk, Wv, bq, bk, bv, pWqkvT, pbqkv,
        x, tok, pos, ph);

    dim3 g_qkv_grid(M_ROWS / 128, QKV_P / 128);   // (16, 9)
    dim3 g_c_grid(M_ROWS / 64, Cc / 128);         // (32, 3)

    for (int l = 0; l < NLl; l++) {
        ln_kernel<<<M_ROWS, 128>>>(ph, ln1g + l * Cc, ln1b + l * Cc, paH);

        g128_fp16_kernel<1><<<g_qkv_grid, 256, LM_SMEM>>>(
            paH, pWqkvT + (size_t)l * QKV_P * Cc, pbqkv + l * QKV_P, pqkvH, QKV_P);

        scores_p_kernel<<<dim3(36, 1, BH), 256>>>(pqkvH, pP, ppsum);
        pv_fp16_kernel<<<dim3(8, BH), 256>>>(pP, pqkvH, ppsum, pattH);

        h16_gemm_kernel<2><<<g_c_grid, 256, H16_SMEM>>>(
            pattH, pWoT + (size_t)l * Cc * Cc, bo + l * Cc, ph, nullptr, Cc);

        ln_kernel<<<M_ROWS, 128>>>(ph, ln2g + l * Cc, ln2b + l * Cc, paH);

        h16_gemm_kernel<1><<<g_c_grid, 256, H16_SMEM>>>(
            paH, pW1T + (size_t)l * Cc * Cc, b1 + l * Cc, pmH, nullptr, Cc);

        if (l == NLl - 1) {
            h16_gemm_kernel<18><<<g_c_grid, 256, H16_SMEM>>>(
                pmH, pW2T + (size_t)l * Cc * Cc, b2 + l * Cc, ph, phH, Cc);
        } else {
            h16_gemm_kernel<2><<<g_c_grid, 256, H16_SMEM>>>(
                pmH, pW2T + (size_t)l * Cc * Cc, b2 + l * Cc, ph, nullptr, Cc);
        }
    }

    // LM head (fp16 tensor cores, 3-stage pipeline, 128x128)
    g128_fp16_kernel<0><<<dim3(M_ROWS / 128, V_PAD / 128), 256, LM_SMEM>>>(
        phH, pWlmH, blm, out, Vv);
}